// round 12
// baseline (speedup 1.0000x reference)
#include <cuda_runtime.h>
#include <cuda_fp16.h>
#include <cstdint>

// Problem constants: C=64 in-channels, T=8 terms, F=64 out.
#define C_DIM 64
#define T_DIM 8
#define F_DIM 64
#define TC_DIM 512  // T*C

#define EMAX 800000
#define NOUTMAX 50176  // 50000 rounded up to multiple of 128

typedef unsigned long long ull;
typedef unsigned int uint;

// ---------------- scratch (__device__ globals; no allocations allowed) ----------
__device__ int   g_is64;
__device__ int   g_count[NOUTMAX];
__device__ ull   g_state[64];                 // decoupled-lookback scan state
__device__ int   g_offsets[NOUTMAX + 1];
__device__ uint  g_rank[EMAX];                // (o << 12) | rank-within-bin
// 32B CSR record per edge: [0..3] = 8 fp16 edge weights, [4] = src index, [5..7] pad.
// One random cache line per edge for both fill's scatter and accum's gather.
__device__ uint  g_rec[(size_t)EMAX * 8];
// M and K^T in fp16 (single plane), K-dim permuted for mma fragment loads.
// Zero-init pad rows (never written) are +0.0h -> safe for mma.
__device__ unsigned short g_Mf[(size_t)NOUTMAX * TC_DIM];
__device__ unsigned short g_Kf[F_DIM * TC_DIM];   // [n][k'] = fp16(Kern[k][n])

// K-dim permutation: within each 16-element group, reorder so lane (t=k-pair idx)
// finds its 4 fragment elements {2t,2t+1,2t+8,2t+9} contiguous at offset t*4.
// Note: preserves bit0, so channel pairs (2j, 2j+1) stay adjacent.
__device__ __forceinline__ int permk(int k) {
    return (k & ~15) | (((k >> 1) & 3) << 2) | (((k >> 3) & 1) << 1) | (k & 1);
}

// ---------------- 4-byte index readers (low word only; values < 2^31) ------------
__device__ __forceinline__ int idx_out32(const void* p, int e) {
    const char* bp = (const char*)p;
    return *(const int*)(bp + ((size_t)e << (3 + g_is64)));
}
__device__ __forceinline__ int idx_in32(const void* p, int e) {
    const char* bp = (const char*)p;
    int sh = 3 + g_is64;
    return *(const int*)(bp + ((size_t)e << sh) + (4 << g_is64));
}

// ---------------- init: zero counters/state + prep K + detect index dtype --------
__global__ void k_init(int nOut, const void* idx, const float* __restrict__ Kf) {
    int i = blockIdx.x * blockDim.x + threadIdx.x;
    if (i == 0) {
        // int64 (nonneg < 2^31): every odd 32-bit word is zero.
        const unsigned* w = (const unsigned*)idx;
        int is64 = 1;
        for (int j = 0; j < 64; j++) {
            if (w[2 * j + 1] != 0u) { is64 = 0; break; }
        }
        g_is64 = is64;
    }
    if (i < nOut) g_count[i] = 0;
    if (i < 64) g_state[i] = 0ull;
    if (i < TC_DIM * F_DIM) {
        int k = i >> 6, n = i & 63;
        g_Kf[(size_t)n * TC_DIM + permk(k)] = __half_as_ushort(__float2half_rn(Kf[i]));
    }
}

// Histogram; store (o << 12) | rank so fill never re-reads idx_out.
// (Degrees are Poisson(E/N_OUT = 16); rank < 4096 by enormous margin.)
__global__ void k_hist(const void* idx, int E) {
    int e = blockIdx.x * blockDim.x + threadIdx.x;
    if (e < E) {
        int o = idx_out32(idx, e);
        uint r = (uint)atomicAdd(&g_count[o], 1);
        g_rank[e] = ((uint)o << 12) | r;
    }
}

// ---------------- single-pass scan, warp-parallel decoupled lookback -------------
#define FLAG_AGG (1ull << 32)
#define FLAG_PFX (2ull << 32)

__global__ void k_scan(int nOut, int E) {
    __shared__ int wsum[32];
    __shared__ int sh_total;
    __shared__ int sh_excl;
    int tid = threadIdx.x;
    int lane = tid & 31, wid = tid >> 5;
    int b = blockIdx.x;
    int i = b * 1024 + tid;
    int v = (i < nOut) ? g_count[i] : 0;

    int s = v;
#pragma unroll
    for (int off = 1; off < 32; off <<= 1) {
        int t = __shfl_up_sync(0xffffffffu, s, off);
        if (lane >= off) s += t;
    }
    if (lane == 31) wsum[wid] = s;
    __syncthreads();
    if (wid == 0) {
        int ws = wsum[lane];
#pragma unroll
        for (int off = 1; off < 32; off <<= 1) {
            int t = __shfl_up_sync(0xffffffffu, ws, off);
            if (lane >= off) ws += t;
        }
        wsum[lane] = ws;
    }
    __syncthreads();
    int incl = s + (wid > 0 ? wsum[wid - 1] : 0);
    if (tid == 1023) sh_total = incl;
    __syncthreads();

    // Publish own aggregate ASAP (prefix directly for block 0).
    if (tid == 0) {
        ull pub = (b == 0 ? FLAG_PFX : FLAG_AGG) | (unsigned)sh_total;
        atomicExch(&g_state[b], pub);
        if (b == 0) sh_excl = 0;
    }
    // Warp-parallel lookback: 32 predecessors per round.
    if (b > 0 && wid == 0) {
        int run = 0;
        int j = b - 1;
        while (true) {
            int si = j - lane;
            ull st;
            if (si >= 0) {
                do { st = atomicAdd(&g_state[si], 0ull); } while ((st >> 32) == 0ull);
            } else {
                st = FLAG_PFX;  // virtual prefix-0 before block 0
            }
            uint pfxmask = __ballot_sync(0xffffffffu, (st >> 32) == 2ull);
            int firstpfx = __ffs(pfxmask) - 1;   // closest predecessor with full prefix
            int limit = firstpfx + 1;            // pfxmask != 0 always (si<0 fallback)
            int contrib = (lane < limit) ? (int)(unsigned)st : 0;
#pragma unroll
            for (int off = 16; off; off >>= 1)
                contrib += __shfl_down_sync(0xffffffffu, contrib, off);
            run += __shfl_sync(0xffffffffu, contrib, 0);
            if (pfxmask != 0u && firstpfx < 32) break;
        }
        if (lane == 0) {
            atomicExch(&g_state[b], FLAG_PFX | (unsigned)(run + sh_total));
            sh_excl = run;
        }
    }
    __syncthreads();

    int excl = sh_excl + incl - v;
    if (i < nOut) g_offsets[i] = excl;
    if (b == 0 && tid == 0) g_offsets[nOut] = E;
}

// Fill CSR (atomic-free): p = offsets[o] + rank. Writes the full 32B record
// (weights + src) -> ONE random cache line per edge.
__global__ void k_fill(const void* idx, const float* __restrict__ edge, int E) {
    int e = blockIdx.x * blockDim.x + threadIdx.x;
    if (e >= E) return;
    uint pr = g_rank[e];
    int o = (int)(pr >> 12);
    int in = idx_in32(idx, e);
    int p = g_offsets[o] + (int)(pr & 0xFFFu);
    uint pk[4];
#pragma unroll
    for (int t = 0; t < 4; t++) {
        float w0 = edge[(size_t)(2 * t) * E + e];
        float w1 = edge[(size_t)(2 * t + 1) * E + e];
        pk[t] = (uint)__half_as_ushort(__float2half_rn(w0))
              | ((uint)__half_as_ushort(__float2half_rn(w1)) << 16);
    }
    uint* rp = g_rec + (size_t)p * 8;
    *reinterpret_cast<uint4*>(rp) = make_uint4(pk[0], pk[1], pk[2], pk[3]);
    rp[4] = (uint)in;
}

// ---------------- edge accumulation: M[o, t*64+c] --------------------------------
// One warp per output; each lane owns channels (2*lane, 2*lane+1).
// R9-proven loop shape; record gather touches one line per edge.
__global__ void k_accum(const float* __restrict__ node, int nOut) {
    int warp = (blockIdx.x * blockDim.x + threadIdx.x) >> 5;
    int lane = threadIdx.x & 31;
    if (warp >= nOut) return;

    int beg = g_offsets[warp];
    int end = g_offsets[warp + 1];

    float sx[T_DIM], sy[T_DIM];
#pragma unroll
    for (int t = 0; t < T_DIM; t++) { sx[t] = 0.f; sy[t] = 0.f; }

#pragma unroll 2
    for (int i = beg; i < end; i++) {
        const uint* rp = g_rec + (size_t)i * 8;
        uint4 ew = *reinterpret_cast<const uint4*>(rp);
        int in = (int)rp[4];
        float2 w0 = __half22float2(*reinterpret_cast<const __half2*>(&ew.x));
        float2 w1 = __half22float2(*reinterpret_cast<const __half2*>(&ew.y));
        float2 w2 = __half22float2(*reinterpret_cast<const __half2*>(&ew.z));
        float2 w3 = __half22float2(*reinterpret_cast<const __half2*>(&ew.w));
        float2 nv = *reinterpret_cast<const float2*>(&node[(size_t)in * C_DIM + lane * 2]);
        sx[0] += w0.x * nv.x; sy[0] += w0.x * nv.y;
        sx[1] += w0.y * nv.x; sy[1] += w0.y * nv.y;
        sx[2] += w1.x * nv.x; sy[2] += w1.x * nv.y;
        sx[3] += w1.y * nv.x; sy[3] += w1.y * nv.y;
        sx[4] += w2.x * nv.x; sy[4] += w2.x * nv.y;
        sx[5] += w2.y * nv.x; sy[5] += w2.y * nv.y;
        sx[6] += w3.x * nv.x; sy[6] += w3.x * nv.y;
        sx[7] += w3.y * nv.x; sy[7] += w3.y * nv.y;
    }

    int pc = permk(lane * 2);  // even; pair (pc, pc+1) is this lane's channel pair
    size_t base = (size_t)warp * TC_DIM + pc;
#pragma unroll
    for (int t = 0; t < T_DIM; t++) {
        uint pk = (uint)__half_as_ushort(__float2half_rn(sx[t]))
                | ((uint)__half_as_ushort(__float2half_rn(sy[t])) << 16);
        *reinterpret_cast<uint*>(&g_Mf[base + (size_t)t * 64]) = pk;
    }
}

// ---------------- GEMM via warp-level mma.sync (single fp16 product) -------------
__device__ __forceinline__ void mma16816(float* d, uint a0, uint a1, uint a2, uint a3,
                                         uint b0, uint b1) {
    asm volatile(
        "mma.sync.aligned.m16n8k16.row.col.f32.f16.f16.f32 "
        "{%0,%1,%2,%3}, {%4,%5,%6,%7}, {%8,%9}, {%0,%1,%2,%3};"
        : "+f"(d[0]), "+f"(d[1]), "+f"(d[2]), "+f"(d[3])
        : "r"(a0), "r"(a1), "r"(a2), "r"(a3), "r"(b0), "r"(b1));
}

__global__ __launch_bounds__(128) void k_gemm(const float* __restrict__ bias,
                                              float* __restrict__ out, int nOut) {
    int tid = threadIdx.x, w = tid >> 5, lane = tid & 31;
    int g = lane >> 2, t = lane & 3;
    int rowbase = blockIdx.x * 128 + w * 32;

    size_t abase = (size_t)(rowbase + g) * TC_DIM + t * 4;
    size_t bbase = (size_t)g * TC_DIM + t * 4;

    float d[2][8][4];
#pragma unroll
    for (int mt = 0; mt < 2; mt++)
#pragma unroll
        for (int nt = 0; nt < 8; nt++)
#pragma unroll
            for (int r = 0; r < 4; r++) d[mt][nt][r] = 0.f;

#pragma unroll 2
    for (int k0 = 0; k0 < TC_DIM; k0 += 16) {
        // A: 4 row-groups (g, g+8, g+16, g+24); each LDG.64 = 4 fp16 fragment elems.
        ull A0 = *reinterpret_cast<const ull*>(g_Mf + abase + k0);
        ull A1 = *reinterpret_cast<const ull*>(g_Mf + abase + 8 * TC_DIM + k0);
        ull A2 = *reinterpret_cast<const ull*>(g_Mf + abase + 16 * TC_DIM + k0);
        ull A3 = *reinterpret_cast<const ull*>(g_Mf + abase + 24 * TC_DIM + k0);
#pragma unroll
        for (int nt = 0; nt < 8; nt++) {
            ull Bv = *reinterpret_cast<const ull*>(g_Kf + bbase + (size_t)nt * 8 * TC_DIM + k0);
            uint b0 = (uint)Bv, b1 = (uint)(Bv >> 32);
            mma16816(d[0][nt], (uint)A0, (uint)A1, (uint)(A0 >> 32), (uint)(A1 >> 32), b0, b1);
            mma16816(d[1][nt], (uint)A2, (uint)A3, (uint)(A2 >> 32), (uint)(A3 >> 32), b0, b1);
        }
    }

    // Epilogue: d0=(g,2t) d1=(g,2t+1) d2=(g+8,2t) d3=(g+8,2t+1) per 16x8 tile.
#pragma unroll
    for (int mt = 0; mt < 2; mt++) {
#pragma unroll
        for (int nt = 0; nt < 8; nt++) {
            int col = nt * 8 + t * 2;
            float2 bv = *reinterpret_cast<const float2*>(bias + col);
            int r0 = rowbase + mt * 16 + g;
            if (r0 < nOut) {
                *reinterpret_cast<float2*>(&out[(size_t)r0 * F_DIM + col]) =
                    make_float2(d[mt][nt][0] + bv.x, d[mt][nt][1] + bv.y);
            }
            int r1 = r0 + 8;
            if (r1 < nOut) {
                *reinterpret_cast<float2*>(&out[(size_t)r1 * F_DIM + col]) =
                    make_float2(d[mt][nt][2] + bv.x, d[mt][nt][3] + bv.y);
            }
        }
    }
}

// ---------------- launch ---------------------------------------------------------
extern "C" void kernel_launch(void* const* d_in, const int* in_sizes, int n_in,
                              void* d_out, int out_size) {
    const float* node = (const float*)d_in[0];
    const float* edge = (const float*)d_in[1];
    const void*  idx  = d_in[2];
    const float* kern = (const float*)d_in[3];
    const float* bias = (const float*)d_in[4];
    float* out = (float*)d_out;

    int E    = in_sizes[1] / T_DIM;   // edge_features is (T, E)
    int nOut = out_size / F_DIM;      // output is (N_OUT, F)
    int nb   = (nOut + 1023) / 1024;  // <= 64

    k_init<<<(nOut + 255) / 256, 256>>>(nOut, idx, kern);
    k_hist<<<(E + 255) / 256, 256>>>(idx, E);
    k_scan<<<nb, 1024>>>(nOut, E);
    k_fill<<<(E + 255) / 256, 256>>>(idx, edge, E);
    k_accum<<<(nOut * 32 + 255) / 256, 256>>>(node, nOut);
    k_gemm<<<(nOut + 127) / 128, 128>>>(bias, out, nOut);
}

// round 13
// speedup vs baseline: 1.1909x; 1.1909x over previous
#include <cuda_runtime.h>
#include <cuda_fp16.h>
#include <cstdint>

// Problem constants: C=64 in-channels, T=8 terms, F=64 out.
#define C_DIM 64
#define T_DIM 8
#define F_DIM 64
#define TC_DIM 512  // T*C

#define EMAX 800000
#define NOUTMAX 50176  // 50000 rounded up to multiple of 128

typedef unsigned long long ull;
typedef unsigned int uint;

// ---------------- scratch (__device__ globals; no allocations allowed) ----------
__device__ int   g_is64;
__device__ int   g_count[NOUTMAX];
__device__ ull   g_state[64];                 // decoupled-lookback scan state
__device__ int   g_offsets[NOUTMAX + 1];
__device__ uint  g_rank[EMAX];                // (o << 12) | rank-within-bin
__device__ int   g_src[EMAX];                 // idx_in per CSR slot
__device__ unsigned short g_edgeW[(size_t)EMAX * T_DIM];  // fp16, 8 per CSR slot
// M and K^T in fp16 (single plane), K-dim permuted for mma fragment loads.
// Zero-init pad rows (never written) are +0.0h -> safe for mma.
__device__ unsigned short g_Mf[(size_t)NOUTMAX * TC_DIM];
__device__ unsigned short g_Kf[F_DIM * TC_DIM];   // [n][k'] = fp16(Kern[k][n])

// K-dim permutation: within each 16-element group, reorder so lane (t=k-pair idx)
// finds its 4 fragment elements {2t,2t+1,2t+8,2t+9} contiguous at offset t*4.
// Note: preserves bit0, so channel pairs (2j, 2j+1) stay adjacent.
__device__ __forceinline__ int permk(int k) {
    return (k & ~15) | (((k >> 1) & 3) << 2) | (((k >> 3) & 1) << 1) | (k & 1);
}

// ---------------- 4-byte index readers (low word only; values < 2^31) ------------
__device__ __forceinline__ int idx_out32(const void* p, int e) {
    const char* bp = (const char*)p;
    return *(const int*)(bp + ((size_t)e << (3 + g_is64)));
}
__device__ __forceinline__ int idx_in32(const void* p, int e) {
    const char* bp = (const char*)p;
    int sh = 3 + g_is64;
    return *(const int*)(bp + ((size_t)e << sh) + (4 << g_is64));
}

// ---------------- init: zero counters/state + prep K + detect index dtype --------
__global__ void k_init(int nOut, const void* idx, const float* __restrict__ Kf) {
    int i = blockIdx.x * blockDim.x + threadIdx.x;
    if (i == 0) {
        // int64 (nonneg < 2^31): every odd 32-bit word is zero.
        const unsigned* w = (const unsigned*)idx;
        int is64 = 1;
        for (int j = 0; j < 64; j++) {
            if (w[2 * j + 1] != 0u) { is64 = 0; break; }
        }
        g_is64 = is64;
    }
    if (i < nOut) g_count[i] = 0;
    if (i < 64) g_state[i] = 0ull;
    if (i < TC_DIM * F_DIM) {
        int k = i >> 6, n = i & 63;
        g_Kf[(size_t)n * TC_DIM + permk(k)] = __half_as_ushort(__float2half_rn(Kf[i]));
    }
}

// Histogram; store (o << 12) | rank so fill never re-reads idx_out.
// (Degrees are Poisson(E/N_OUT = 16); rank < 4096 by enormous margin.)
__global__ void k_hist(const void* idx, int E) {
    int e = blockIdx.x * blockDim.x + threadIdx.x;
    if (e < E) {
        int o = idx_out32(idx, e);
        uint r = (uint)atomicAdd(&g_count[o], 1);
        g_rank[e] = ((uint)o << 12) | r;
    }
}

// ---------------- single-pass scan, warp-parallel decoupled lookback -------------
#define FLAG_AGG (1ull << 32)
#define FLAG_PFX (2ull << 32)

__global__ void k_scan(int nOut, int E) {
    __shared__ int wsum[32];
    __shared__ int sh_total;
    __shared__ int sh_excl;
    int tid = threadIdx.x;
    int lane = tid & 31, wid = tid >> 5;
    int b = blockIdx.x;
    int i = b * 1024 + tid;
    int v = (i < nOut) ? g_count[i] : 0;

    int s = v;
#pragma unroll
    for (int off = 1; off < 32; off <<= 1) {
        int t = __shfl_up_sync(0xffffffffu, s, off);
        if (lane >= off) s += t;
    }
    if (lane == 31) wsum[wid] = s;
    __syncthreads();
    if (wid == 0) {
        int ws = wsum[lane];
#pragma unroll
        for (int off = 1; off < 32; off <<= 1) {
            int t = __shfl_up_sync(0xffffffffu, ws, off);
            if (lane >= off) ws += t;
        }
        wsum[lane] = ws;
    }
    __syncthreads();
    int incl = s + (wid > 0 ? wsum[wid - 1] : 0);
    if (tid == 1023) sh_total = incl;
    __syncthreads();

    // Publish own aggregate (prefix directly for block 0).
    if (tid == 0) {
        ull pub = (b == 0 ? FLAG_PFX : FLAG_AGG) | (unsigned)sh_total;
        atomicExch(&g_state[b], pub);
        if (b == 0) sh_excl = 0;
    }
    // Warp-parallel lookback: 32 predecessors per round; lane 0 = closest.
    if (b > 0 && wid == 0) {
        int run = 0;
        int j = b - 1;
        while (true) {
            int si = j - lane;
            ull st;
            if (si >= 0) {
                do { st = atomicAdd(&g_state[si], 0ull); } while ((st >> 32) == 0ull);
            } else {
                st = FLAG_PFX;  // virtual prefix-0 below block 0 (value 0)
            }
            uint pfxmask = __ballot_sync(0xffffffffu, (st >> 32) == 2ull);
            int firstpfx = (pfxmask != 0u) ? (__ffs(pfxmask) - 1) : 32;
            int limit = (pfxmask != 0u) ? (firstpfx + 1) : 32;
            int contrib = (lane < limit) ? (int)(unsigned)st : 0;
#pragma unroll
            for (int off = 16; off; off >>= 1)
                contrib += __shfl_down_sync(0xffffffffu, contrib, off);
            run += __shfl_sync(0xffffffffu, contrib, 0);
            if (pfxmask != 0u) break;
            j -= 32;  // no prefix in this window: consumed 32 aggregates, move on
        }
        if (lane == 0) {
            atomicExch(&g_state[b], FLAG_PFX | (unsigned)(run + sh_total));
            sh_excl = run;
        }
    }
    __syncthreads();

    int excl = sh_excl + incl - v;
    if (i < nOut) g_offsets[i] = excl;
    if (b == 0 && tid == 0) g_offsets[nOut] = E;
}

// Fill CSR (atomic-free): p = offsets[o] + rank, with o/rank unpacked from
// g_rank. Pre-gathers edge weights transposed to (slot, 8) in fp16.
__global__ void k_fill(const void* idx, const float* __restrict__ edge, int E) {
    int e = blockIdx.x * blockDim.x + threadIdx.x;
    if (e >= E) return;
    uint pr = g_rank[e];
    int o = (int)(pr >> 12);
    int in = idx_in32(idx, e);
    int p = g_offsets[o] + (int)(pr & 0xFFFu);
    g_src[p] = in;
    uint pk[4];
#pragma unroll
    for (int t = 0; t < 4; t++) {
        float w0 = edge[(size_t)(2 * t) * E + e];
        float w1 = edge[(size_t)(2 * t + 1) * E + e];
        pk[t] = (uint)__half_as_ushort(__float2half_rn(w0))
              | ((uint)__half_as_ushort(__float2half_rn(w1)) << 16);
    }
    *reinterpret_cast<uint4*>(g_edgeW + (size_t)p * 8) =
        make_uint4(pk[0], pk[1], pk[2], pk[3]);
}

// ---------------- edge accumulation: M[o, t*64+c] --------------------------------
// One warp per output; each lane owns channels (2*lane, 2*lane+1).  (R9-proven loop)
__global__ void k_accum(const float* __restrict__ node, int nOut) {
    int warp = (blockIdx.x * blockDim.x + threadIdx.x) >> 5;
    int lane = threadIdx.x & 31;
    if (warp >= nOut) return;

    int beg = g_offsets[warp];
    int end = g_offsets[warp + 1];

    float sx[T_DIM], sy[T_DIM];
#pragma unroll
    for (int t = 0; t < T_DIM; t++) { sx[t] = 0.f; sy[t] = 0.f; }

#pragma unroll 2
    for (int i = beg; i < end; i++) {
        int in = g_src[i];
        uint4 ew = *reinterpret_cast<const uint4*>(g_edgeW + (size_t)i * 8);
        float2 w0 = __half22float2(*reinterpret_cast<const __half2*>(&ew.x));
        float2 w1 = __half22float2(*reinterpret_cast<const __half2*>(&ew.y));
        float2 w2 = __half22float2(*reinterpret_cast<const __half2*>(&ew.z));
        float2 w3 = __half22float2(*reinterpret_cast<const __half2*>(&ew.w));
        float2 nv = *reinterpret_cast<const float2*>(&node[(size_t)in * C_DIM + lane * 2]);
        sx[0] += w0.x * nv.x; sy[0] += w0.x * nv.y;
        sx[1] += w0.y * nv.x; sy[1] += w0.y * nv.y;
        sx[2] += w1.x * nv.x; sy[2] += w1.x * nv.y;
        sx[3] += w1.y * nv.x; sy[3] += w1.y * nv.y;
        sx[4] += w2.x * nv.x; sy[4] += w2.x * nv.y;
        sx[5] += w2.y * nv.x; sy[5] += w2.y * nv.y;
        sx[6] += w3.x * nv.x; sy[6] += w3.x * nv.y;
        sx[7] += w3.y * nv.x; sy[7] += w3.y * nv.y;
    }

    int pc = permk(lane * 2);  // even; pair (pc, pc+1) is this lane's channel pair
    size_t base = (size_t)warp * TC_DIM + pc;
#pragma unroll
    for (int t = 0; t < T_DIM; t++) {
        uint pk = (uint)__half_as_ushort(__float2half_rn(sx[t]))
                | ((uint)__half_as_ushort(__float2half_rn(sy[t])) << 16);
        *reinterpret_cast<uint*>(&g_Mf[base + (size_t)t * 64]) = pk;
    }
}

// ---------------- GEMM via warp-level mma.sync (single fp16 product) -------------
__device__ __forceinline__ void mma16816(float* d, uint a0, uint a1, uint a2, uint a3,
                                         uint b0, uint b1) {
    asm volatile(
        "mma.sync.aligned.m16n8k16.row.col.f32.f16.f16.f32 "
        "{%0,%1,%2,%3}, {%4,%5,%6,%7}, {%8,%9}, {%0,%1,%2,%3};"
        : "+f"(d[0]), "+f"(d[1]), "+f"(d[2]), "+f"(d[3])
        : "r"(a0), "r"(a1), "r"(a2), "r"(a3), "r"(b0), "r"(b1));
}

__global__ __launch_bounds__(128) void k_gemm(const float* __restrict__ bias,
                                              float* __restrict__ out, int nOut) {
    int tid = threadIdx.x, w = tid >> 5, lane = tid & 31;
    int g = lane >> 2, t = lane & 3;
    int rowbase = blockIdx.x * 128 + w * 32;

    size_t abase = (size_t)(rowbase + g) * TC_DIM + t * 4;
    size_t bbase = (size_t)g * TC_DIM + t * 4;

    float d[2][8][4];
#pragma unroll
    for (int mt = 0; mt < 2; mt++)
#pragma unroll
        for (int nt = 0; nt < 8; nt++)
#pragma unroll
            for (int r = 0; r < 4; r++) d[mt][nt][r] = 0.f;

#pragma unroll 2
    for (int k0 = 0; k0 < TC_DIM; k0 += 16) {
        // A: 4 row-groups (g, g+8, g+16, g+24); each LDG.64 = 4 fp16 fragment elems.
        ull A0 = *reinterpret_cast<const ull*>(g_Mf + abase + k0);
        ull A1 = *reinterpret_cast<const ull*>(g_Mf + abase + 8 * TC_DIM + k0);
        ull A2 = *reinterpret_cast<const ull*>(g_Mf + abase + 16 * TC_DIM + k0);
        ull A3 = *reinterpret_cast<const ull*>(g_Mf + abase + 24 * TC_DIM + k0);
#pragma unroll
        for (int nt = 0; nt < 8; nt++) {
            ull Bv = *reinterpret_cast<const ull*>(g_Kf + bbase + (size_t)nt * 8 * TC_DIM + k0);
            uint b0 = (uint)Bv, b1 = (uint)(Bv >> 32);
            mma16816(d[0][nt], (uint)A0, (uint)A1, (uint)(A0 >> 32), (uint)(A1 >> 32), b0, b1);
            mma16816(d[1][nt], (uint)A2, (uint)A3, (uint)(A2 >> 32), (uint)(A3 >> 32), b0, b1);
        }
    }

    // Epilogue: d0=(g,2t) d1=(g,2t+1) d2=(g+8,2t) d3=(g+8,2t+1) per 16x8 tile.
#pragma unroll
    for (int mt = 0; mt < 2; mt++) {
#pragma unroll
        for (int nt = 0; nt < 8; nt++) {
            int col = nt * 8 + t * 2;
            float2 bv = *reinterpret_cast<const float2*>(bias + col);
            int r0 = rowbase + mt * 16 + g;
            if (r0 < nOut) {
                *reinterpret_cast<float2*>(&out[(size_t)r0 * F_DIM + col]) =
                    make_float2(d[mt][nt][0] + bv.x, d[mt][nt][1] + bv.y);
            }
            int r1 = r0 + 8;
            if (r1 < nOut) {
                *reinterpret_cast<float2*>(&out[(size_t)r1 * F_DIM + col]) =
                    make_float2(d[mt][nt][2] + bv.x, d[mt][nt][3] + bv.y);
            }
        }
    }
}

// ---------------- launch ---------------------------------------------------------
extern "C" void kernel_launch(void* const* d_in, const int* in_sizes, int n_in,
                              void* d_out, int out_size) {
    const float* node = (const float*)d_in[0];
    const float* edge = (const float*)d_in[1];
    const void*  idx  = d_in[2];
    const float* kern = (const float*)d_in[3];
    const float* bias = (const float*)d_in[4];
    float* out = (float*)d_out;

    int E    = in_sizes[1] / T_DIM;   // edge_features is (T, E)
    int nOut = out_size / F_DIM;      // output is (N_OUT, F)
    int nb   = (nOut + 1023) / 1024;  // <= 64

    k_init<<<(nOut + 255) / 256, 256>>>(nOut, idx, kern);
    k_hist<<<(E + 255) / 256, 256>>>(idx, E);
    k_scan<<<nb, 1024>>>(nOut, E);
    k_fill<<<(E + 255) / 256, 256>>>(idx, edge, E);
    k_accum<<<(nOut * 32 + 255) / 256, 256>>>(node, nOut);
    k_gemm<<<(nOut + 127) / 128, 128>>>(bias, out, nOut);
}